// round 7
// baseline (speedup 1.0000x reference)
#include <cuda_runtime.h>
#include <cuda_fp16.h>
#include <stdint.h>
#include <math.h>

// ---------------------------------------------------------------- scratch
__device__ float g_logits[8 * 8 * 32 * 32];   // [b][n][h][w] raw logits
__device__ float g_vsum[8 * 8 * 32 * 32];     // [b][n][x][y]
__device__ float g_wvsum[8 * 512];
__device__ __half g_xh[8192 * 512];
__device__ __half g_wqh[512 * 512];
__device__ __half g_wkh[512 * 512];

// ---------------------------------------------------------------- helpers
__device__ __forceinline__ uint32_t smem_u32(const void* p) {
    uint32_t a;
    asm("{ .reg .u64 t; cvta.to.shared.u64 t, %1; cvt.u32.u64 %0, t; }" : "=r"(a) : "l"(p));
    return a;
}
__device__ __forceinline__ void ldsm4(uint32_t* r, uint32_t addr) {
    asm volatile("ldmatrix.sync.aligned.m8n8.x4.shared.b16 {%0,%1,%2,%3}, [%4];"
                 : "=r"(r[0]), "=r"(r[1]), "=r"(r[2]), "=r"(r[3]) : "r"(addr));
}
__device__ __forceinline__ void mma16816(float* d, const uint32_t* a, const uint32_t* b) {
    asm volatile(
        "mma.sync.aligned.m16n8k16.row.col.f32.f16.f16.f32 "
        "{%0,%1,%2,%3}, {%4,%5,%6,%7}, {%8,%9}, {%0,%1,%2,%3};"
        : "+f"(d[0]), "+f"(d[1]), "+f"(d[2]), "+f"(d[3])
        : "r"(a[0]), "r"(a[1]), "r"(a[2]), "r"(a[3]), "r"(b[0]), "r"(b[1]));
}
__device__ __forceinline__ void cp_async16(uint32_t dst, const void* src) {
    asm volatile("cp.async.cg.shared.global [%0], [%1], 16;"
                 :: "r"(dst), "l"(__cvta_generic_to_global(src)) : "memory");
}
__device__ __forceinline__ void cp_commit_wait() {
    asm volatile("cp.async.commit_group;\ncp.async.wait_group 0;" ::: "memory");
}

// ---------------------------------------------------------------- kernel: fused fp32->fp16 convert
// covers x (1048576 float4), wq (65536), wk (65536): total 1179648 float4
__global__ void cvt_all_kernel(const float* __restrict__ x,
                               const float* __restrict__ wq,
                               const float* __restrict__ wk,
                               __half* __restrict__ xh,
                               __half* __restrict__ wqh,
                               __half* __restrict__ wkh) {
    int i = blockIdx.x * blockDim.x + threadIdx.x;
    const float* src;
    __half* dst;
    int j;
    if (i < 1048576)      { src = x;  dst = xh;  j = i; }
    else if (i < 1114112) { src = wq; dst = wqh; j = i - 1048576; }
    else                  { src = wk; dst = wkh; j = i - 1114112; }
    float4 v = ((const float4*)src)[j];
    ((ushort4*)dst)[j] = make_ushort4(
        __half_as_ushort(__float2half(v.x)), __half_as_ushort(__float2half(v.y)),
        __half_as_ushort(__float2half(v.z)), __half_as_ushort(__float2half(v.w)));
}

// ---------------------------------------------------------------- kernel: wvsum (row-parallel)
// grid 32 = head(8) x colchunk(4); 512 threads = 128 cols x 4 row-groups of 16.
__global__ void wvsum_kernel(const float* __restrict__ wv) {
    __shared__ float part[4][128];
    int n = blockIdx.x >> 2;
    int cloc = threadIdx.x & 127;
    int rg = threadIdx.x >> 7;                 // 0..3
    int c = (blockIdx.x & 3) * 128 + cloc;
    const float* base = wv + (size_t)(n * 64 + rg * 16) * 512 + c;
    float s = 0.f;
#pragma unroll 16
    for (int d = 0; d < 16; ++d) s += base[d * 512];
    part[rg][cloc] = s;
    __syncthreads();
    if (rg == 0)
        g_wvsum[n * 512 + c] = part[0][cloc] + part[1][cloc] + part[2][cloc] + part[3][cloc];
}

// ---------------------------------------------------------------- kernel: vsum (fp32)
__global__ void vsum_kernel(const float* __restrict__ x) {
    int p = blockIdx.x * 8 + (threadIdx.x >> 5);
    int lane = threadIdx.x & 31;
    const float4* xr = (const float4*)(x + (size_t)p * 512);
    float4 xv[4];
#pragma unroll
    for (int t = 0; t < 4; ++t) xv[t] = xr[lane * 4 + t];
    float acc[8];
#pragma unroll
    for (int n = 0; n < 8; ++n) {
        const float4* wr = (const float4*)(g_wvsum + n * 512);
        float s = 0.f;
#pragma unroll
        for (int t = 0; t < 4; ++t) {
            float4 w = wr[lane * 4 + t];
            s = fmaf(xv[t].x, w.x, s); s = fmaf(xv[t].y, w.y, s);
            s = fmaf(xv[t].z, w.z, s); s = fmaf(xv[t].w, w.w, s);
        }
#pragma unroll
        for (int o = 16; o > 0; o >>= 1) s += __shfl_xor_sync(0xffffffffu, s, o);
        acc[n] = s;
    }
    if (lane < 8) {
        float v = acc[0];
#pragma unroll
        for (int n = 1; n < 8; ++n) if (lane == n) v = acc[n];
        int b = p >> 10, pos = p & 1023;
        g_vsum[(b * 8 + lane) * 1024 + pos] = v;
    }
}

// ---------------------------------------------------------------- kernel: QK, single-pass fp16 mma
// block = (128-pixel tile) x (head). 256 threads / 8 warps, 16 rows per warp.
static constexpr int RS   = 144;
static constexpr int XH_O = 0;              // X  (128 x 72)
static constexpr int QH_O = 18432;          // Wq (64 x 72)
static constexpr int KH_O = 27648;          // Wk
static constexpr int SM_TOTAL = 36864;

__global__ void __launch_bounds__(256, 4)
qk_kernel() {
    extern __shared__ char smem[];
    const uint32_t sb = smem_u32(smem);
    const int tid  = threadIdx.x;
    const int lane = tid & 31;
    const int wid  = tid >> 5;
    const int tile = blockIdx.x;      // 0..63
    const int head = blockIdx.y;      // 0..7
    const int pix0 = tile * 128;

    const uint32_t a_off = sb + (uint32_t)(wid * 16 + (lane & 15)) * RS + ((lane >> 4) << 4);
    const uint32_t b_row = (lane & 7) + ((lane >> 4) << 3);
    const uint32_t b_off = sb + b_row * RS + (((lane >> 3) & 1) << 4);

    float accQ[8][4], accK[8][4];
#pragma unroll
    for (int i = 0; i < 8; ++i)
#pragma unroll
        for (int j = 0; j < 4; ++j) { accQ[i][j] = 0.f; accK[i][j] = 0.f; }

    for (int ch = 0; ch < 8; ++ch) {
        const int c0 = ch * 64;
        // X: 128 rows x 8 chunks = 1024 cp; 4 per thread
#pragma unroll
        for (int g = 0; g < 4; ++g) {
            int idx = tid + g * 256;
            int r = idx >> 3, cc = idx & 7;
            uint32_t so = (uint32_t)r * RS + cc * 16;
            cp_async16(sb + XH_O + so, g_xh + (size_t)(pix0 + r) * 512 + c0 + cc * 8);
        }
        // Wq/Wk: 64 rows x 8 chunks = 512 cp each; 2 iters
#pragma unroll
        for (int g = 0; g < 2; ++g) {
            int idx = tid + g * 256;
            int r = idx >> 3, cc = idx & 7;
            uint32_t so = (uint32_t)r * RS + cc * 16;
            const size_t gg = (size_t)(head * 64 + r) * 512 + c0 + cc * 8;
            cp_async16(sb + QH_O + so, g_wqh + gg);
            cp_async16(sb + KH_O + so, g_wkh + gg);
        }
        cp_commit_wait();
        __syncthreads();

#pragma unroll
        for (int ks = 0; ks < 4; ++ks) {
            const uint32_t ko = ks * 32;
            uint32_t ah[4];
            ldsm4(ah, a_off + XH_O + ko);
#pragma unroll
            for (int np = 0; np < 4; ++np) {
                const uint32_t off = b_off + np * (16 * RS) + ko;
                uint32_t bq[4], bk[4];
                ldsm4(bq, off + QH_O);
                ldsm4(bk, off + KH_O);
                mma16816(accQ[np * 2],     ah, bq);
                mma16816(accQ[np * 2 + 1], ah, bq + 2);
                mma16816(accK[np * 2],     ah, bk);
                mma16816(accK[np * 2 + 1], ah, bk + 2);
            }
        }
        __syncthreads();
    }

    // epilogue: per-pixel dot over the 64 j's
    float plo = 0.f, phi = 0.f;
#pragma unroll
    for (int nt = 0; nt < 8; ++nt) {
        plo = fmaf(accQ[nt][0], accK[nt][0], plo);
        plo = fmaf(accQ[nt][1], accK[nt][1], plo);
        phi = fmaf(accQ[nt][2], accK[nt][2], phi);
        phi = fmaf(accQ[nt][3], accK[nt][3], phi);
    }
    plo += __shfl_xor_sync(0xffffffffu, plo, 1);
    plo += __shfl_xor_sync(0xffffffffu, plo, 2);
    phi += __shfl_xor_sync(0xffffffffu, phi, 1);
    phi += __shfl_xor_sync(0xffffffffu, phi, 2);
    if ((lane & 3) == 0) {
        int r0 = wid * 16 + (lane >> 2);
        int p0 = pix0 + r0;
        int p1 = p0 + 8;
        int b0 = p0 >> 10, b1 = p1 >> 10;
        g_logits[(b0 * 8 + head) * 1024 + (p0 & 1023)] = plo;
        g_logits[(b1 * 8 + head) * 1024 + (p1 & 1023)] = phi;
    }
}

// ---------------------------------------------------------------- kernel: fused softmax + outer store
__global__ void outer_kernel(float* __restrict__ out) {
    int r = blockIdx.x;        // (b*8+n)*32 + h
    int bn = r >> 5;
    int h = r & 31;
    __shared__ float4 vs[256];
    __shared__ float ws[32];
    vs[threadIdx.x] = ((const float4*)(g_vsum + bn * 1024))[threadIdx.x];
    if (threadIdx.x < 32) {
        int lane = threadIdx.x;
        float v = g_logits[bn * 1024 + h * 32 + lane] * 0.125f;
        float m = v;
#pragma unroll
        for (int o = 16; o > 0; o >>= 1) m = fmaxf(m, __shfl_xor_sync(0xffffffffu, m, o));
        float e = __expf(v - m);
        float s = e;
#pragma unroll
        for (int o = 16; o > 0; o >>= 1) s += __shfl_xor_sync(0xffffffffu, s, o);
        ws[lane] = e / s;
    }
    __syncthreads();
    float4 v = vs[threadIdx.x];
    float4* o = (float4*)out + (size_t)r * 8192;
#pragma unroll
    for (int w = 0; w < 32; ++w) {
        float s = ws[w];
        float4 t = make_float4(s * v.x, s * v.y, s * v.z, s * v.w);
        __stcs(&o[w * 256 + threadIdx.x], t);
    }
}

// ----------------------------------------------------------------
extern "C" void kernel_launch(void* const* d_in, const int* in_sizes, int n_in,
                              void* d_out, int out_size) {
    const float* x  = (const float*)d_in[0];
    const float* wq = (const float*)d_in[1];
    const float* wk = (const float*)d_in[2];
    const float* wv = (const float*)d_in[3];
    float* out = (float*)d_out;

    cudaFuncSetAttribute(qk_kernel, cudaFuncAttributeMaxDynamicSharedMemorySize, SM_TOTAL);

    __half *xh, *wqh, *wkh;
    cudaGetSymbolAddress((void**)&xh, g_xh);
    cudaGetSymbolAddress((void**)&wqh, g_wqh);
    cudaGetSymbolAddress((void**)&wkh, g_wkh);

    cvt_all_kernel<<<4608, 256>>>(x, wq, wk, xh, wqh, wkh);
    wvsum_kernel<<<32, 512>>>(wv);
    vsum_kernel<<<1024, 256>>>(x);
    qk_kernel<<<dim3(64, 8), 256, SM_TOTAL>>>();
    outer_kernel<<<2048, 256>>>(out);
}

// round 8
// speedup vs baseline: 1.5189x; 1.5189x over previous
#include <cuda_runtime.h>
#include <cuda_fp16.h>
#include <stdint.h>
#include <math.h>

// ---------------------------------------------------------------- scratch
__device__ float g_logits[8 * 8 * 32 * 32];   // [b][n][h][w] raw logits
__device__ float g_vsum[8 * 8 * 32 * 32];     // [b][n][x][y]
__device__ float g_wvsum[8 * 512];
__device__ __half g_xh[8192 * 512];
__device__ __half g_wqh[512 * 512];
__device__ __half g_wkh[512 * 512];

// ---------------------------------------------------------------- helpers
__device__ __forceinline__ uint32_t smem_u32(const void* p) {
    uint32_t a;
    asm("{ .reg .u64 t; cvta.to.shared.u64 t, %1; cvt.u32.u64 %0, t; }" : "=r"(a) : "l"(p));
    return a;
}
__device__ __forceinline__ void ldsm4(uint32_t* r, uint32_t addr) {
    asm volatile("ldmatrix.sync.aligned.m8n8.x4.shared.b16 {%0,%1,%2,%3}, [%4];"
                 : "=r"(r[0]), "=r"(r[1]), "=r"(r[2]), "=r"(r[3]) : "r"(addr));
}
__device__ __forceinline__ void mma16816(float* d, const uint32_t* a, const uint32_t* b) {
    asm volatile(
        "mma.sync.aligned.m16n8k16.row.col.f32.f16.f16.f32 "
        "{%0,%1,%2,%3}, {%4,%5,%6,%7}, {%8,%9}, {%0,%1,%2,%3};"
        : "+f"(d[0]), "+f"(d[1]), "+f"(d[2]), "+f"(d[3])
        : "r"(a[0]), "r"(a[1]), "r"(a[2]), "r"(a[3]), "r"(b[0]), "r"(b[1]));
}
__device__ __forceinline__ void cp_async16(uint32_t dst, const void* src) {
    asm volatile("cp.async.cg.shared.global [%0], [%1], 16;"
                 :: "r"(dst), "l"(__cvta_generic_to_global(src)) : "memory");
}
__device__ __forceinline__ void cp_commit_wait() {
    asm volatile("cp.async.commit_group;\ncp.async.wait_group 0;" ::: "memory");
}

// ---------------------------------------------------------------- kernel: fused fp32->fp16 convert
__global__ void cvt_all_kernel(const float* __restrict__ x,
                               const float* __restrict__ wq,
                               const float* __restrict__ wk,
                               __half* __restrict__ xh,
                               __half* __restrict__ wqh,
                               __half* __restrict__ wkh) {
    int i = blockIdx.x * blockDim.x + threadIdx.x;
    const float* src;
    __half* dst;
    int j;
    if (i < 1048576)      { src = x;  dst = xh;  j = i; }
    else if (i < 1114112) { src = wq; dst = wqh; j = i - 1048576; }
    else                  { src = wk; dst = wkh; j = i - 1114112; }
    float4 v = ((const float4*)src)[j];
    ((ushort4*)dst)[j] = make_ushort4(
        __half_as_ushort(__float2half(v.x)), __half_as_ushort(__float2half(v.y)),
        __half_as_ushort(__float2half(v.z)), __half_as_ushort(__float2half(v.w)));
}

// ---------------------------------------------------------------- kernel: wvsum (row-parallel)
__global__ void wvsum_kernel(const float* __restrict__ wv) {
    __shared__ float part[4][128];
    int n = blockIdx.x >> 2;
    int cloc = threadIdx.x & 127;
    int rg = threadIdx.x >> 7;
    int c = (blockIdx.x & 3) * 128 + cloc;
    const float* base = wv + (size_t)(n * 64 + rg * 16) * 512 + c;
    float s = 0.f;
#pragma unroll 16
    for (int d = 0; d < 16; ++d) s += base[d * 512];
    part[rg][cloc] = s;
    __syncthreads();
    if (rg == 0)
        g_wvsum[n * 512 + c] = part[0][cloc] + part[1][cloc] + part[2][cloc] + part[3][cloc];
}

// ---------------------------------------------------------------- kernel: vsum (fp32)
__global__ void vsum_kernel(const float* __restrict__ x) {
    int p = blockIdx.x * 8 + (threadIdx.x >> 5);
    int lane = threadIdx.x & 31;
    const float4* xr = (const float4*)(x + (size_t)p * 512);
    float4 xv[4];
#pragma unroll
    for (int t = 0; t < 4; ++t) xv[t] = xr[lane * 4 + t];
    float acc[8];
#pragma unroll
    for (int n = 0; n < 8; ++n) {
        const float4* wr = (const float4*)(g_wvsum + n * 512);
        float s = 0.f;
#pragma unroll
        for (int t = 0; t < 4; ++t) {
            float4 w = wr[lane * 4 + t];
            s = fmaf(xv[t].x, w.x, s); s = fmaf(xv[t].y, w.y, s);
            s = fmaf(xv[t].z, w.z, s); s = fmaf(xv[t].w, w.w, s);
        }
#pragma unroll
        for (int o = 16; o > 0; o >>= 1) s += __shfl_xor_sync(0xffffffffu, s, o);
        acc[n] = s;
    }
    if (lane < 8) {
        float v = acc[0];
#pragma unroll
        for (int n = 1; n < 8; ++n) if (lane == n) v = acc[n];
        int b = p >> 10, pos = p & 1023;
        g_vsum[(b * 8 + lane) * 1024 + pos] = v;
    }
}

// ---------------------------------------------------------------- kernel: QK, single-pass fp16 mma
// block = (128-pixel tile) x (head). 256 threads / 8 warps, 16 rows per warp.
// occupancy 2 (NOT 4): 64 accumulator floats must stay in registers.
static constexpr int RS   = 144;
static constexpr int XH_O = 0;              // X  (128 x 72)
static constexpr int QH_O = 18432;          // Wq (64 x 72)
static constexpr int KH_O = 27648;          // Wk
static constexpr int SM_TOTAL = 36864;

__global__ void __launch_bounds__(256, 2)
qk_kernel() {
    extern __shared__ char smem[];
    const uint32_t sb = smem_u32(smem);
    const int tid  = threadIdx.x;
    const int lane = tid & 31;
    const int wid  = tid >> 5;
    const int tile = blockIdx.x;      // 0..63
    const int head = blockIdx.y;      // 0..7
    const int pix0 = tile * 128;

    const uint32_t a_off = sb + (uint32_t)(wid * 16 + (lane & 15)) * RS + ((lane >> 4) << 4);
    const uint32_t b_row = (lane & 7) + ((lane >> 4) << 3);
    const uint32_t b_off = sb + b_row * RS + (((lane >> 3) & 1) << 4);

    float accQ[8][4], accK[8][4];
#pragma unroll
    for (int i = 0; i < 8; ++i)
#pragma unroll
        for (int j = 0; j < 4; ++j) { accQ[i][j] = 0.f; accK[i][j] = 0.f; }

    for (int ch = 0; ch < 8; ++ch) {
        const int c0 = ch * 64;
        // X: 128 rows x 8 chunks = 1024 cp; 4 per thread
#pragma unroll
        for (int g = 0; g < 4; ++g) {
            int idx = tid + g * 256;
            int r = idx >> 3, cc = idx & 7;
            uint32_t so = (uint32_t)r * RS + cc * 16;
            cp_async16(sb + XH_O + so, g_xh + (size_t)(pix0 + r) * 512 + c0 + cc * 8);
        }
        // Wq/Wk: 64 rows x 8 chunks = 512 cp each
#pragma unroll
        for (int g = 0; g < 2; ++g) {
            int idx = tid + g * 256;
            int r = idx >> 3, cc = idx & 7;
            uint32_t so = (uint32_t)r * RS + cc * 16;
            const size_t gg = (size_t)(head * 64 + r) * 512 + c0 + cc * 8;
            cp_async16(sb + QH_O + so, g_wqh + gg);
            cp_async16(sb + KH_O + so, g_wkh + gg);
        }
        cp_commit_wait();
        __syncthreads();

#pragma unroll
        for (int ks = 0; ks < 4; ++ks) {
            const uint32_t ko = ks * 32;
            uint32_t ah[4];
            ldsm4(ah, a_off + XH_O + ko);
#pragma unroll
            for (int np = 0; np < 4; ++np) {
                const uint32_t off = b_off + np * (16 * RS) + ko;
                uint32_t bq[4], bk[4];
                ldsm4(bq, off + QH_O);
                ldsm4(bk, off + KH_O);
                mma16816(accQ[np * 2],     ah, bq);
                mma16816(accQ[np * 2 + 1], ah, bq + 2);
                mma16816(accK[np * 2],     ah, bk);
                mma16816(accK[np * 2 + 1], ah, bk + 2);
            }
        }
        __syncthreads();
    }

    // epilogue: per-pixel dot over the 64 j's
    float plo = 0.f, phi = 0.f;
#pragma unroll
    for (int nt = 0; nt < 8; ++nt) {
        plo = fmaf(accQ[nt][0], accK[nt][0], plo);
        plo = fmaf(accQ[nt][1], accK[nt][1], plo);
        phi = fmaf(accQ[nt][2], accK[nt][2], phi);
        phi = fmaf(accQ[nt][3], accK[nt][3], phi);
    }
    plo += __shfl_xor_sync(0xffffffffu, plo, 1);
    plo += __shfl_xor_sync(0xffffffffu, plo, 2);
    phi += __shfl_xor_sync(0xffffffffu, phi, 1);
    phi += __shfl_xor_sync(0xffffffffu, phi, 2);
    if ((lane & 3) == 0) {
        int r0 = wid * 16 + (lane >> 2);
        int p0 = pix0 + r0;
        int p1 = p0 + 8;
        int b0 = p0 >> 10, b1 = p1 >> 10;
        g_logits[(b0 * 8 + head) * 1024 + (p0 & 1023)] = plo;
        g_logits[(b1 * 8 + head) * 1024 + (p1 & 1023)] = phi;
    }
}

// ---------------------------------------------------------------- kernel: fused softmax + outer store
__global__ void outer_kernel(float* __restrict__ out) {
    int r = blockIdx.x;        // (b*8+n)*32 + h
    int bn = r >> 5;
    int h = r & 31;
    __shared__ float4 vs[256];
    __shared__ float ws[32];
    vs[threadIdx.x] = ((const float4*)(g_vsum + bn * 1024))[threadIdx.x];
    if (threadIdx.x < 32) {
        int lane = threadIdx.x;
        float v = g_logits[bn * 1024 + h * 32 + lane] * 0.125f;
        float m = v;
#pragma unroll
        for (int o = 16; o > 0; o >>= 1) m = fmaxf(m, __shfl_xor_sync(0xffffffffu, m, o));
        float e = __expf(v - m);
        float s = e;
#pragma unroll
        for (int o = 16; o > 0; o >>= 1) s += __shfl_xor_sync(0xffffffffu, s, o);
        ws[lane] = e / s;
    }
    __syncthreads();
    float4 v = vs[threadIdx.x];
    float4* o = (float4*)out + (size_t)r * 8192;
#pragma unroll
    for (int w = 0; w < 32; ++w) {
        float s = ws[w];
        float4 t = make_float4(s * v.x, s * v.y, s * v.z, s * v.w);
        __stcs(&o[w * 256 + threadIdx.x], t);
    }
}

// ----------------------------------------------------------------
extern "C" void kernel_launch(void* const* d_in, const int* in_sizes, int n_in,
                              void* d_out, int out_size) {
    const float* x  = (const float*)d_in[0];
    const float* wq = (const float*)d_in[1];
    const float* wk = (const float*)d_in[2];
    const float* wv = (const float*)d_in[3];
    float* out = (float*)d_out;

    cudaFuncSetAttribute(qk_kernel, cudaFuncAttributeMaxDynamicSharedMemorySize, SM_TOTAL);

    __half *xh, *wqh, *wkh;
    cudaGetSymbolAddress((void**)&xh, g_xh);
    cudaGetSymbolAddress((void**)&wqh, g_wqh);
    cudaGetSymbolAddress((void**)&wkh, g_wkh);

    cvt_all_kernel<<<4608, 256>>>(x, wq, wk, xh, wqh, wkh);
    wvsum_kernel<<<32, 512>>>(wv);
    vsum_kernel<<<1024, 256>>>(x);
    qk_kernel<<<dim3(64, 8), 256, SM_TOTAL>>>();
    outer_kernel<<<2048, 256>>>(out);
}

// round 9
// speedup vs baseline: 1.6528x; 1.0882x over previous
#include <cuda_runtime.h>
#include <cuda_fp16.h>
#include <stdint.h>
#include <math.h>

// ---------------------------------------------------------------- scratch
__device__ float g_vsum[8 * 8 * 32 * 32];     // [b][n][x][y]
__device__ float g_wvsum[8 * 512];
__device__ __half g_xh[8192 * 512];
__device__ __half g_wqh[512 * 512];
__device__ __half g_wkh[512 * 512];

// ---------------------------------------------------------------- helpers
__device__ __forceinline__ uint32_t smem_u32(const void* p) {
    uint32_t a;
    asm("{ .reg .u64 t; cvta.to.shared.u64 t, %1; cvt.u32.u64 %0, t; }" : "=r"(a) : "l"(p));
    return a;
}
__device__ __forceinline__ void ldsm4(uint32_t* r, uint32_t addr) {
    asm volatile("ldmatrix.sync.aligned.m8n8.x4.shared.b16 {%0,%1,%2,%3}, [%4];"
                 : "=r"(r[0]), "=r"(r[1]), "=r"(r[2]), "=r"(r[3]) : "r"(addr));
}
__device__ __forceinline__ void mma16816(float* d, const uint32_t* a, const uint32_t* b) {
    asm volatile(
        "mma.sync.aligned.m16n8k16.row.col.f32.f16.f16.f32 "
        "{%0,%1,%2,%3}, {%4,%5,%6,%7}, {%8,%9}, {%0,%1,%2,%3};"
        : "+f"(d[0]), "+f"(d[1]), "+f"(d[2]), "+f"(d[3])
        : "r"(a[0]), "r"(a[1]), "r"(a[2]), "r"(a[3]), "r"(b[0]), "r"(b[1]));
}
__device__ __forceinline__ void cp_async16(uint32_t dst, const void* src) {
    asm volatile("cp.async.cg.shared.global [%0], [%1], 16;"
                 :: "r"(dst), "l"(__cvta_generic_to_global(src)) : "memory");
}
__device__ __forceinline__ void cp_commit_wait() {
    asm volatile("cp.async.commit_group;\ncp.async.wait_group 0;" ::: "memory");
}

// ---------------------------------------------------------------- kernel: fused fp32->fp16 convert
__global__ void cvt_all_kernel(const float* __restrict__ x,
                               const float* __restrict__ wq,
                               const float* __restrict__ wk,
                               __half* __restrict__ xh,
                               __half* __restrict__ wqh,
                               __half* __restrict__ wkh) {
    int i = blockIdx.x * blockDim.x + threadIdx.x;
    const float* src;
    __half* dst;
    int j;
    if (i < 1048576)      { src = x;  dst = xh;  j = i; }
    else if (i < 1114112) { src = wq; dst = wqh; j = i - 1048576; }
    else                  { src = wk; dst = wkh; j = i - 1114112; }
    float4 v = ((const float4*)src)[j];
    ((ushort4*)dst)[j] = make_ushort4(
        __half_as_ushort(__float2half(v.x)), __half_as_ushort(__float2half(v.y)),
        __half_as_ushort(__float2half(v.z)), __half_as_ushort(__float2half(v.w)));
}

// ---------------------------------------------------------------- kernel: wvsum (row-parallel)
__global__ void wvsum_kernel(const float* __restrict__ wv) {
    __shared__ float part[4][128];
    int n = blockIdx.x >> 2;
    int cloc = threadIdx.x & 127;
    int rg = threadIdx.x >> 7;
    int c = (blockIdx.x & 3) * 128 + cloc;
    const float* base = wv + (size_t)(n * 64 + rg * 16) * 512 + c;
    float s = 0.f;
#pragma unroll 16
    for (int d = 0; d < 16; ++d) s += base[d * 512];
    part[rg][cloc] = s;
    __syncthreads();
    if (rg == 0)
        g_wvsum[n * 512 + c] = part[0][cloc] + part[1][cloc] + part[2][cloc] + part[3][cloc];
}

// ---------------------------------------------------------------- kernel: vsum (fp32)
__global__ void vsum_kernel(const float* __restrict__ x) {
    int p = blockIdx.x * 8 + (threadIdx.x >> 5);
    int lane = threadIdx.x & 31;
    const float4* xr = (const float4*)(x + (size_t)p * 512);
    float4 xv[4];
#pragma unroll
    for (int t = 0; t < 4; ++t) xv[t] = xr[lane * 4 + t];
    float acc[8];
#pragma unroll
    for (int n = 0; n < 8; ++n) {
        const float4* wr = (const float4*)(g_wvsum + n * 512);
        float s = 0.f;
#pragma unroll
        for (int t = 0; t < 4; ++t) {
            float4 w = wr[lane * 4 + t];
            s = fmaf(xv[t].x, w.x, s); s = fmaf(xv[t].y, w.y, s);
            s = fmaf(xv[t].z, w.z, s); s = fmaf(xv[t].w, w.w, s);
        }
#pragma unroll
        for (int o = 16; o > 0; o >>= 1) s += __shfl_xor_sync(0xffffffffu, s, o);
        acc[n] = s;
    }
    if (lane < 8) {
        float v = acc[0];
#pragma unroll
        for (int n = 1; n < 8; ++n) if (lane == n) v = acc[n];
        int b = p >> 10, pos = p & 1023;
        g_vsum[(b * 8 + lane) * 1024 + pos] = v;
    }
}

// ---------------------------------------------------------------- kernel: fused QK + softmax + outer store
// block = (128-pixel tile) x (head); 128 pixels = 4 complete softmax rows of one b.
// 256 threads / 8 warps, 16 pixel-rows per warp.
static constexpr int RS   = 144;
static constexpr int XH_O = 0;              // X  (128 x 72)
static constexpr int QH_O = 18432;          // Wq (64 x 72)
static constexpr int KH_O = 27648;          // Wk
static constexpr int SM_TOTAL = 36864;

__global__ void __launch_bounds__(256, 2)
qk_kernel(float* __restrict__ out) {
    extern __shared__ char smem[];
    __shared__ float ws[128];       // per-pixel softmax weights
    __shared__ float4 vsm[256];     // vsum row for (b, head)
    const uint32_t sb = smem_u32(smem);
    const int tid  = threadIdx.x;
    const int lane = tid & 31;
    const int wid  = tid >> 5;
    const int tile = blockIdx.x;      // 0..63
    const int head = blockIdx.y;      // 0..7
    const int pix0 = tile * 128;
    const int b    = pix0 >> 10;

    const uint32_t a_off = sb + (uint32_t)(wid * 16 + (lane & 15)) * RS + ((lane >> 4) << 4);
    const uint32_t b_row = (lane & 7) + ((lane >> 4) << 3);
    const uint32_t b_off = sb + b_row * RS + (((lane >> 3) & 1) << 4);

    // prefetch vsum row while MMAs run
    vsm[tid] = ((const float4*)(g_vsum + (size_t)(b * 8 + head) * 1024))[tid];

    float accQ[8][4], accK[8][4];
#pragma unroll
    for (int i = 0; i < 8; ++i)
#pragma unroll
        for (int j = 0; j < 4; ++j) { accQ[i][j] = 0.f; accK[i][j] = 0.f; }

    for (int ch = 0; ch < 8; ++ch) {
        const int c0 = ch * 64;
#pragma unroll
        for (int g = 0; g < 4; ++g) {
            int idx = tid + g * 256;
            int r = idx >> 3, cc = idx & 7;
            uint32_t so = (uint32_t)r * RS + cc * 16;
            cp_async16(sb + XH_O + so, g_xh + (size_t)(pix0 + r) * 512 + c0 + cc * 8);
        }
#pragma unroll
        for (int g = 0; g < 2; ++g) {
            int idx = tid + g * 256;
            int r = idx >> 3, cc = idx & 7;
            uint32_t so = (uint32_t)r * RS + cc * 16;
            const size_t gg = (size_t)(head * 64 + r) * 512 + c0 + cc * 8;
            cp_async16(sb + QH_O + so, g_wqh + gg);
            cp_async16(sb + KH_O + so, g_wkh + gg);
        }
        cp_commit_wait();
        __syncthreads();

#pragma unroll
        for (int ks = 0; ks < 4; ++ks) {
            const uint32_t ko = ks * 32;
            uint32_t ah[4];
            ldsm4(ah, a_off + XH_O + ko);
#pragma unroll
            for (int np = 0; np < 4; ++np) {
                const uint32_t off = b_off + np * (16 * RS) + ko;
                uint32_t bq[4], bk[4];
                ldsm4(bq, off + QH_O);
                ldsm4(bk, off + KH_O);
                mma16816(accQ[np * 2],     ah, bq);
                mma16816(accQ[np * 2 + 1], ah, bq + 2);
                mma16816(accK[np * 2],     ah, bk);
                mma16816(accK[np * 2 + 1], ah, bk + 2);
            }
        }
        __syncthreads();
    }

    // ---- per-pixel logit: dot over the 64 j's
    float plo = 0.f, phi = 0.f;
#pragma unroll
    for (int nt = 0; nt < 8; ++nt) {
        plo = fmaf(accQ[nt][0], accK[nt][0], plo);
        plo = fmaf(accQ[nt][1], accK[nt][1], plo);
        phi = fmaf(accQ[nt][2], accK[nt][2], phi);
        phi = fmaf(accQ[nt][3], accK[nt][3], phi);
    }
    plo += __shfl_xor_sync(0xffffffffu, plo, 1);
    plo += __shfl_xor_sync(0xffffffffu, plo, 2);
    phi += __shfl_xor_sync(0xffffffffu, phi, 1);
    phi += __shfl_xor_sync(0xffffffffu, phi, 2);
    if ((lane & 3) == 0) {
        int i0 = wid * 16 + (lane >> 2);
        ws[i0] = plo;
        ws[i0 + 8] = phi;
    }
    __syncthreads();

    // ---- softmax: 4 rows of 32 (warps 0-3)
    if (tid < 128) {
        float v = ws[tid] * 0.125f;
        float m = v;
#pragma unroll
        for (int o = 16; o > 0; o >>= 1) m = fmaxf(m, __shfl_xor_sync(0xffffffffu, m, o));
        float e = __expf(v - m);
        float s = e;
#pragma unroll
        for (int o = 16; o > 0; o >>= 1) s += __shfl_xor_sync(0xffffffffu, s, o);
        ws[tid] = e / s;
    }
    __syncthreads();

    // ---- outer-product store: 128 rows x 1024 floats
    const float4 v = vsm[tid];
    float4* o = (float4*)out + ((size_t)(b * 8 + head) * 1024 + (pix0 & 1023)) * 256 + tid;
#pragma unroll 8
    for (int row = 0; row < 128; ++row) {
        float s = ws[row];
        __stcs(o + (size_t)row * 256, make_float4(s * v.x, s * v.y, s * v.z, s * v.w));
    }
}

// ----------------------------------------------------------------
extern "C" void kernel_launch(void* const* d_in, const int* in_sizes, int n_in,
                              void* d_out, int out_size) {
    const float* x  = (const float*)d_in[0];
    const float* wq = (const float*)d_in[1];
    const float* wk = (const float*)d_in[2];
    const float* wv = (const float*)d_in[3];
    float* out = (float*)d_out;

    cudaFuncSetAttribute(qk_kernel, cudaFuncAttributeMaxDynamicSharedMemorySize, SM_TOTAL);

    __half *xh, *wqh, *wkh;
    cudaGetSymbolAddress((void**)&xh, g_xh);
    cudaGetSymbolAddress((void**)&wqh, g_wqh);
    cudaGetSymbolAddress((void**)&wkh, g_wkh);

    cvt_all_kernel<<<4608, 256>>>(x, wq, wk, xh, wqh, wkh);
    wvsum_kernel<<<32, 512>>>(wv);
    vsum_kernel<<<1024, 256>>>(x);
    qk_kernel<<<dim3(64, 8), 256, SM_TOTAL>>>(out);
}

// round 10
// speedup vs baseline: 1.7430x; 1.0546x over previous
#include <cuda_runtime.h>
#include <cuda_fp16.h>
#include <stdint.h>
#include <math.h>

// ---------------------------------------------------------------- scratch
__device__ float g_vsum[8 * 8 * 32 * 32];     // [b][n][x][y]
__device__ float g_wvsum[8 * 512];
__device__ __half g_xh[8192 * 512];
__device__ __half g_wqh[512 * 512];
__device__ __half g_wkh[512 * 512];

// ---------------------------------------------------------------- helpers
__device__ __forceinline__ uint32_t smem_u32(const void* p) {
    uint32_t a;
    asm("{ .reg .u64 t; cvta.to.shared.u64 t, %1; cvt.u32.u64 %0, t; }" : "=r"(a) : "l"(p));
    return a;
}
__device__ __forceinline__ void ldsm4(uint32_t* r, uint32_t addr) {
    asm volatile("ldmatrix.sync.aligned.m8n8.x4.shared.b16 {%0,%1,%2,%3}, [%4];"
                 : "=r"(r[0]), "=r"(r[1]), "=r"(r[2]), "=r"(r[3]) : "r"(addr));
}
__device__ __forceinline__ void mma16816(float* d, const uint32_t* a, const uint32_t* b) {
    asm volatile(
        "mma.sync.aligned.m16n8k16.row.col.f32.f16.f16.f32 "
        "{%0,%1,%2,%3}, {%4,%5,%6,%7}, {%8,%9}, {%0,%1,%2,%3};"
        : "+f"(d[0]), "+f"(d[1]), "+f"(d[2]), "+f"(d[3])
        : "r"(a[0]), "r"(a[1]), "r"(a[2]), "r"(a[3]), "r"(b[0]), "r"(b[1]));
}
__device__ __forceinline__ void cp_async16(uint32_t dst, const void* src) {
    asm volatile("cp.async.cg.shared.global [%0], [%1], 16;"
                 :: "r"(dst), "l"(__cvta_generic_to_global(src)) : "memory");
}
__device__ __forceinline__ void cp_commit_wait() {
    asm volatile("cp.async.commit_group;\ncp.async.wait_group 0;" ::: "memory");
}

// ---------------------------------------------------------------- kernel: prep_w = wvsum + W fp16 cvt
// blocks 0..31: wvsum; blocks 32..287: cvt wq/wk (131072 float4, 1 per thread)
__global__ void prep_w_kernel(const float* __restrict__ wv,
                              const float* __restrict__ wq,
                              const float* __restrict__ wk,
                              __half* __restrict__ wqh,
                              __half* __restrict__ wkh) {
    if (blockIdx.x < 32) {
        __shared__ float part[4][128];
        int n = blockIdx.x >> 2;
        int cloc = threadIdx.x & 127;
        int rg = threadIdx.x >> 7;
        int c = (blockIdx.x & 3) * 128 + cloc;
        const float* base = wv + (size_t)(n * 64 + rg * 16) * 512 + c;
        float s = 0.f;
#pragma unroll 16
        for (int d = 0; d < 16; ++d) s += base[d * 512];
        part[rg][cloc] = s;
        __syncthreads();
        if (rg == 0)
            g_wvsum[n * 512 + c] = part[0][cloc] + part[1][cloc] + part[2][cloc] + part[3][cloc];
        return;
    }
    int i = (blockIdx.x - 32) * 512 + threadIdx.x;   // 0..131071
    const float* src;
    __half* dst;
    int j;
    if (i < 65536) { src = wq; dst = wqh; j = i; }
    else           { src = wk; dst = wkh; j = i - 65536; }
    float4 v = ((const float4*)src)[j];
    ((ushort4*)dst)[j] = make_ushort4(
        __half_as_ushort(__float2half(v.x)), __half_as_ushort(__float2half(v.y)),
        __half_as_ushort(__float2half(v.z)), __half_as_ushort(__float2half(v.w)));
}

// ---------------------------------------------------------------- kernel: prep_x = x fp16 cvt + vsum
// warp per pixel; 1024 blocks x 256 threads
__global__ void prep_x_kernel(const float* __restrict__ x, __half* __restrict__ xh) {
    int p = blockIdx.x * 8 + (threadIdx.x >> 5);
    int lane = threadIdx.x & 31;
    const float4* xr = (const float4*)(x + (size_t)p * 512);
    float4 xv[4];
#pragma unroll
    for (int t = 0; t < 4; ++t) xv[t] = xr[lane * 4 + t];
    // fp16 store
    ushort4* xo = (ushort4*)(xh + (size_t)p * 512);
#pragma unroll
    for (int t = 0; t < 4; ++t) {
        xo[lane * 4 + t] = make_ushort4(
            __half_as_ushort(__float2half(xv[t].x)), __half_as_ushort(__float2half(xv[t].y)),
            __half_as_ushort(__float2half(xv[t].z)), __half_as_ushort(__float2half(xv[t].w)));
    }
    // vsum dots
    float acc[8];
#pragma unroll
    for (int n = 0; n < 8; ++n) {
        const float4* wr = (const float4*)(g_wvsum + n * 512);
        float s = 0.f;
#pragma unroll
        for (int t = 0; t < 4; ++t) {
            float4 w = wr[lane * 4 + t];
            s = fmaf(xv[t].x, w.x, s); s = fmaf(xv[t].y, w.y, s);
            s = fmaf(xv[t].z, w.z, s); s = fmaf(xv[t].w, w.w, s);
        }
#pragma unroll
        for (int o = 16; o > 0; o >>= 1) s += __shfl_xor_sync(0xffffffffu, s, o);
        acc[n] = s;
    }
    if (lane < 8) {
        float v = acc[0];
#pragma unroll
        for (int n = 1; n < 8; ++n) if (lane == n) v = acc[n];
        int b = p >> 10, pos = p & 1023;
        g_vsum[(b * 8 + lane) * 1024 + pos] = v;
    }
}

// ---------------------------------------------------------------- kernel: pipelined fused QK+softmax+store
// 256 blocks (one resident wave). block bx: tile = bx & 63, headA = bx >> 6, headB = headA + 4.
// Unit A: MMA -> softmax. Unit B: MMA loop with A's stores interleaved -> softmax -> store B.
static constexpr int RS   = 144;
static constexpr int XH_O = 0;              // X  (128 x 72)
static constexpr int QH_O = 18432;          // Wq (64 x 72)
static constexpr int KH_O = 27648;          // Wk
static constexpr int SM_TOTAL = 36864;

__global__ void __launch_bounds__(256, 2)
qk_kernel(float* __restrict__ out) {
    extern __shared__ char smem[];
    __shared__ float  ws[2][128];
    __shared__ float4 vsm[2][256];
    const uint32_t sb = smem_u32(smem);
    const int tid  = threadIdx.x;
    const int lane = tid & 31;
    const int wid  = tid >> 5;
    const int tile  = blockIdx.x & 63;
    const int headA = blockIdx.x >> 6;        // 0..3
    const int pix0 = tile * 128;
    const int b    = pix0 >> 10;

    const uint32_t a_off = sb + (uint32_t)(wid * 16 + (lane & 15)) * RS + ((lane >> 4) << 4);
    const uint32_t b_row = (lane & 7) + ((lane >> 4) << 3);
    const uint32_t b_off = sb + b_row * RS + (((lane >> 3) & 1) << 4);

    // prefetch both vsum rows (thread-local use: no sync needed)
    vsm[0][tid] = ((const float4*)(g_vsum + (size_t)(b * 8 + headA) * 1024))[tid];
    vsm[1][tid] = ((const float4*)(g_vsum + (size_t)(b * 8 + headA + 4) * 1024))[tid];

    // output slab bases (float4 units)
    float4* oA = (float4*)out + ((size_t)(b * 8 + headA) * 1024 + (pix0 & 1023)) * 256 + tid;
    float4* oB = oA + (size_t)4 * 1024 * 256;   // head + 4

    for (int u = 0; u < 2; ++u) {
        const int head = headA + u * 4;
        float accQ[8][4], accK[8][4];
#pragma unroll
        for (int i = 0; i < 8; ++i)
#pragma unroll
            for (int j = 0; j < 4; ++j) { accQ[i][j] = 0.f; accK[i][j] = 0.f; }

        for (int ch = 0; ch < 8; ++ch) {
            const int c0 = ch * 64;
#pragma unroll
            for (int g = 0; g < 4; ++g) {
                int idx = tid + g * 256;
                int r = idx >> 3, cc = idx & 7;
                uint32_t so = (uint32_t)r * RS + cc * 16;
                cp_async16(sb + XH_O + so, g_xh + (size_t)(pix0 + r) * 512 + c0 + cc * 8);
            }
#pragma unroll
            for (int g = 0; g < 2; ++g) {
                int idx = tid + g * 256;
                int r = idx >> 3, cc = idx & 7;
                uint32_t so = (uint32_t)r * RS + cc * 16;
                const size_t gg = (size_t)(head * 64 + r) * 512 + c0 + cc * 8;
                cp_async16(sb + QH_O + so, g_wqh + gg);
                cp_async16(sb + KH_O + so, g_wkh + gg);
            }
            // interleave unit A's store burst (16 rows) into unit B's load/MMA pipe
            if (u == 1) {
                const float4 vA = vsm[0][tid];
#pragma unroll
                for (int r = 0; r < 16; ++r) {
                    int row = ch * 16 + r;
                    float s = ws[0][row];
                    __stcs(oA + (size_t)row * 256,
                           make_float4(s * vA.x, s * vA.y, s * vA.z, s * vA.w));
                }
            }
            cp_commit_wait();
            __syncthreads();

#pragma unroll
            for (int ks = 0; ks < 4; ++ks) {
                const uint32_t ko = ks * 32;
                uint32_t ah[4];
                ldsm4(ah, a_off + XH_O + ko);
#pragma unroll
                for (int np = 0; np < 4; ++np) {
                    const uint32_t off = b_off + np * (16 * RS) + ko;
                    uint32_t bq[4], bk[4];
                    ldsm4(bq, off + QH_O);
                    ldsm4(bk, off + KH_O);
                    mma16816(accQ[np * 2],     ah, bq);
                    mma16816(accQ[np * 2 + 1], ah, bq + 2);
                    mma16816(accK[np * 2],     ah, bk);
                    mma16816(accK[np * 2 + 1], ah, bk + 2);
                }
            }
            __syncthreads();
        }

        // per-pixel logit: dot over the 64 j's
        float plo = 0.f, phi = 0.f;
#pragma unroll
        for (int nt = 0; nt < 8; ++nt) {
            plo = fmaf(accQ[nt][0], accK[nt][0], plo);
            plo = fmaf(accQ[nt][1], accK[nt][1], plo);
            phi = fmaf(accQ[nt][2], accK[nt][2], phi);
            phi = fmaf(accQ[nt][3], accK[nt][3], phi);
        }
        plo += __shfl_xor_sync(0xffffffffu, plo, 1);
        plo += __shfl_xor_sync(0xffffffffu, plo, 2);
        phi += __shfl_xor_sync(0xffffffffu, phi, 1);
        phi += __shfl_xor_sync(0xffffffffu, phi, 2);
        if ((lane & 3) == 0) {
            int i0 = wid * 16 + (lane >> 2);
            ws[u][i0] = plo;
            ws[u][i0 + 8] = phi;
        }
        __syncthreads();

        // softmax: 4 rows of 32
        if (tid < 128) {
            float v = ws[u][tid] * 0.125f;
            float m = v;
#pragma unroll
            for (int o = 16; o > 0; o >>= 1) m = fmaxf(m, __shfl_xor_sync(0xffffffffu, m, o));
            float e = __expf(v - m);
            float s = e;
#pragma unroll
            for (int o = 16; o > 0; o >>= 1) s += __shfl_xor_sync(0xffffffffu, s, o);
            ws[u][tid] = e / s;
        }
        __syncthreads();
    }

    // store unit B (unit A was streamed during B's MMA loop)
    const float4 vB = vsm[1][tid];
#pragma unroll 8
    for (int row = 0; row < 128; ++row) {
        float s = ws[1][row];
        __stcs(oB + (size_t)row * 256, make_float4(s * vB.x, s * vB.y, s * vB.z, s * vB.w));
    }
}

// ----------------------------------------------------------------
extern "C" void kernel_launch(void* const* d_in, const int* in_sizes, int n_in,
                              void* d_out, int out_size) {
    const float* x  = (const float*)d_in[0];
    const float* wq = (const float*)d_in[1];
    const float* wk = (const float*)d_in[2];
    const float* wv = (const float*)d_in[3];
    float* out = (float*)d_out;

    cudaFuncSetAttribute(qk_kernel, cudaFuncAttributeMaxDynamicSharedMemorySize, SM_TOTAL);

    __half *xh, *wqh, *wkh;
    cudaGetSymbolAddress((void**)&xh, g_xh);
    cudaGetSymbolAddress((void**)&wqh, g_wqh);
    cudaGetSymbolAddress((void**)&wkh, g_wkh);

    prep_w_kernel<<<288, 512>>>(wv, wq, wk, wqh, wkh);
    prep_x_kernel<<<1024, 256>>>(x, xh);
    qk_kernel<<<256, 256, SM_TOTAL>>>(out);
}